// round 15
// baseline (speedup 1.0000x reference)
#include <cuda_runtime.h>
#include <cuda_bf16.h>
#include <math.h>
#include <stdint.h>

#define BATCH   4
#define TLEN    512
#define EDIM    1024
#define VOCAB_N 32000
#define BEAM_N  64
#define RANK_N  32
#define MROWS   (BATCH * TLEN)

__device__ __align__(16) int8_t g_A1[MROWS * EDIM];
__device__ __align__(16) int8_t g_A0[MROWS * EDIM];
__device__ __align__(16) int8_t g_B1[VOCAB_N * EDIM];
__device__ __align__(16) int8_t g_B0[VOCAB_N * EDIM];
__device__ float g_sA[MROWS];
__device__ float g_sB[VOCAB_N];
__device__ int   g_beams[MROWS * BEAM_N];
__device__ float g_bemit[MROWS * BEAM_N];
__device__ __align__(16) float g_tm[BATCH * (TLEN - 1) * BEAM_N * BEAM_N]; // exp(trans)

// ---------------------------------------------------------------- helpers --
__device__ __forceinline__ uint32_t s2u(const void* p) {
    uint32_t a;
    asm("{ .reg .u64 t; cvta.to.shared.u64 t, %1; cvt.u32.u64 %0, t; }" : "=r"(a) : "l"(p));
    return a;
}
__device__ __forceinline__ void cpasync16(uint32_t s, const void* g) {
    asm volatile("cp.async.cg.shared.global [%0], [%1], 16;" :: "r"(s), "l"(g) : "memory");
}
__device__ __forceinline__ void ldm4(uint32_t* f, uint32_t addr) {
    asm volatile("ldmatrix.sync.aligned.m8n8.x4.shared.b16 {%0,%1,%2,%3}, [%4];"
        : "=r"(f[0]), "=r"(f[1]), "=r"(f[2]), "=r"(f[3]) : "r"(addr));
}
__device__ __forceinline__ void imma16832(int* d, const uint32_t* a,
                                          uint32_t b0, uint32_t b1) {
    asm volatile("mma.sync.aligned.m16n8k32.row.col.s32.s8.s8.s32 "
        "{%0,%1,%2,%3}, {%4,%5,%6,%7}, {%8,%9}, {%0,%1,%2,%3};"
        : "+r"(d[0]), "+r"(d[1]), "+r"(d[2]), "+r"(d[3])
        : "r"(a[0]), "r"(a[1]), "r"(a[2]), "r"(a[3]), "r"(b0), "r"(b1));
}

// ============================ 0) fp32 -> int8 2-limb quantization ===========
__global__ void __launch_bounds__(256)
quant_kernel(const float* __restrict__ src, int8_t* __restrict__ o1,
             int8_t* __restrict__ o0, float* __restrict__ scale)
{
    int row = blockIdx.x, tid = threadIdx.x, lane = tid & 31;
    __shared__ float wmax[8];
    __shared__ float ss;
    const float4* srow = (const float4*)(src + (size_t)row * EDIM);
    float4 v = srow[tid];
    float m = fmaxf(fmaxf(fabsf(v.x), fabsf(v.y)), fmaxf(fabsf(v.z), fabsf(v.w)));
#pragma unroll
    for (int o = 16; o > 0; o >>= 1) m = fmaxf(m, __shfl_xor_sync(0xffffffffu, m, o));
    if (lane == 0) wmax[tid >> 5] = m;
    __syncthreads();
    if (tid == 0) {
        float mm = wmax[0];
#pragma unroll
        for (int i = 1; i < 8; i++) mm = fmaxf(mm, wmax[i]);
        ss = fmaxf(mm, 1e-20f) / 16256.f;
        scale[row] = ss;
    }
    __syncthreads();
    float inv = 1.f / ss;
    int q[4];
    q[0] = __float2int_rn(v.x * inv); q[1] = __float2int_rn(v.y * inv);
    q[2] = __float2int_rn(v.z * inv); q[3] = __float2int_rn(v.w * inv);
    char h[4], l[4];
#pragma unroll
    for (int j = 0; j < 4; j++) {
        int hi = (q[j] + 64) >> 7;
        h[j] = (char)hi;
        l[j] = (char)(q[j] - (hi << 7));
    }
    ((char4*)o1)[(size_t)row * 256 + tid] = make_char4(h[0], h[1], h[2], h[3]);
    ((char4*)o0)[(size_t)row * 256 + tid] = make_char4(l[0], l[1], l[2], l[3]);
}

// ============================ 1) int8 IMMA GEMM (R13 pipeline shape) ========
// C = (16384*A1B1 + 128*(A1B0+A0B1)) * sA * sB + bias, terms INTERLEAVED.
// CTA 128x128, 512 thr, warp tile 32x32, BK=64 B, 2-stage cp.async, 16 iters.
#define ROW_B 80
#define MAT_BYTES (128 * ROW_B)           // 10240
#define STAGE_BYTES (4 * MAT_BYTES)       // 40960: A1|A0|B1|B0
#define GEMM_SMEM (2 * STAGE_BYTES)       // 81920
#define KITERS2 16

__device__ __forceinline__ void load_stage2(uint32_t sbase, int buf, int it,
                                            int tid, int row0, int col0) {
    uint32_t st = sbase + buf * STAGE_BYTES;
    int kk = it * 64;
#pragma unroll
    for (int j = 0; j < 4; j++) {
        int cid = tid + j * 512;          // 2048 16B chunks
        int mat = cid >> 9;               // 0:A1 1:A0 2:B1 3:B0
        int rc  = cid & 511;
        int r = rc >> 2, c = rc & 3;      // 128 rows x 4 chunks (64B data)
        const int8_t* gp;
        if (mat == 0)      gp = g_A1 + (size_t)(row0 + r) * EDIM + kk + c * 16;
        else if (mat == 1) gp = g_A0 + (size_t)(row0 + r) * EDIM + kk + c * 16;
        else if (mat == 2) gp = g_B1 + (size_t)(col0 + r) * EDIM + kk + c * 16;
        else               gp = g_B0 + (size_t)(col0 + r) * EDIM + kk + c * 16;
        cpasync16(st + (uint32_t)(mat * MAT_BYTES + r * ROW_B + c * 16), gp);
    }
    asm volatile("cp.async.commit_group;" ::: "memory");
}

__global__ void __launch_bounds__(512, 1)
gemm_imma(const float* __restrict__ bias, float* __restrict__ C)
{
    extern __shared__ char smem[];
    uint32_t sbase = s2u(smem);
    int tid = threadIdx.x, lane = tid & 31, wid = tid >> 5;

    // swizzle: groups of 10 col-blocks x 16 row-blocks for L2 reuse
    int bid = blockIdx.x;
    int grp = bid / 160, w = bid % 160;
    int row0 = (w & 15) * 128;
    int col0 = (grp * 10 + (w >> 4)) * 128;

    int warp_m = wid & 3;                 // 4 -> 32 rows each
    int warp_n = wid >> 2;                // 4 -> 32 cols each

    int acc1[2][4][4], accX[2][4][4];
#pragma unroll
    for (int mi = 0; mi < 2; mi++)
#pragma unroll
        for (int ni = 0; ni < 4; ni++)
#pragma unroll
            for (int q = 0; q < 4; q++) { acc1[mi][ni][q] = 0; accX[mi][ni][q] = 0; }

    load_stage2(sbase, 0, 0, tid, row0, col0);
    load_stage2(sbase, 1, 1, tid, row0, col0);

    uint32_t aoff0 = (uint32_t)(warp_m * 32 + (lane & 15)) * ROW_B + ((lane >> 4) * 16);
    uint32_t aoff1 = aoff0 + 16 * ROW_B;
    uint32_t boff0 = (uint32_t)(warp_n * 32 + (lane & 7) + ((lane >> 4) << 3)) * ROW_B
                   + (((lane >> 3) & 1) * 16);
    uint32_t boff1 = boff0 + 16 * ROW_B;

    for (int it = 0; it < KITERS2; it++) {
        if (it < KITERS2 - 1) asm volatile("cp.async.wait_group 1;" ::: "memory");
        else                  asm volatile("cp.async.wait_group 0;" ::: "memory");
        __syncthreads();

        uint32_t st = sbase + (uint32_t)((it & 1) * STAGE_BYTES);
#pragma unroll
        for (int ks = 0; ks < 2; ks++) {
            uint32_t kb = ks * 32;
            uint32_t a1f[2][4], a0f[2][4], bhf[2][4], blf[2][4];
            ldm4(a1f[0], st + 0 * MAT_BYTES + aoff0 + kb);
            ldm4(a1f[1], st + 0 * MAT_BYTES + aoff1 + kb);
            ldm4(a0f[0], st + 1 * MAT_BYTES + aoff0 + kb);
            ldm4(a0f[1], st + 1 * MAT_BYTES + aoff1 + kb);
            ldm4(bhf[0], st + 2 * MAT_BYTES + boff0 + kb);
            ldm4(bhf[1], st + 2 * MAT_BYTES + boff1 + kb);
            ldm4(blf[0], st + 3 * MAT_BYTES + boff0 + kb);
            ldm4(blf[1], st + 3 * MAT_BYTES + boff1 + kb);
#pragma unroll
            for (int mi = 0; mi < 2; mi++)
#pragma unroll
                for (int nh = 0; nh < 2; nh++) {
                    imma16832(acc1[mi][nh*2+0], a1f[mi], bhf[nh][0], bhf[nh][1]);
                    imma16832(acc1[mi][nh*2+1], a1f[mi], bhf[nh][2], bhf[nh][3]);
                    imma16832(accX[mi][nh*2+0], a1f[mi], blf[nh][0], blf[nh][1]);
                    imma16832(accX[mi][nh*2+1], a1f[mi], blf[nh][2], blf[nh][3]);
                    imma16832(accX[mi][nh*2+0], a0f[mi], bhf[nh][0], bhf[nh][1]);
                    imma16832(accX[mi][nh*2+1], a0f[mi], bhf[nh][2], bhf[nh][3]);
                }
        }
        __syncthreads();
        if (it + 2 < KITERS2) load_stage2(sbase, it & 1, it + 2, tid, row0, col0);
    }

    // epilogue: C = (16384*acc1 + 128*accX) * sA[row]*sB[col] + bias[col]
    int rb = row0 + warp_m * 32 + (lane >> 2);
    int cb = col0 + warp_n * 32 + (lane & 3) * 2;
    float sa[2][2];
#pragma unroll
    for (int mi = 0; mi < 2; mi++) {
        sa[mi][0] = g_sA[rb + mi * 16];
        sa[mi][1] = g_sA[rb + mi * 16 + 8];
    }
#pragma unroll
    for (int ni = 0; ni < 4; ni++) {
        int c = cb + ni * 8;
        float sb0 = g_sB[c], sb1 = g_sB[c + 1];
        float b0 = bias[c], b1 = bias[c + 1];
#pragma unroll
        for (int mi = 0; mi < 2; mi++) {
            int r1 = rb + mi * 16;
            float r00 = 16384.f * (float)acc1[mi][ni][0] + 128.f * (float)accX[mi][ni][0];
            float r01 = 16384.f * (float)acc1[mi][ni][1] + 128.f * (float)accX[mi][ni][1];
            float r10 = 16384.f * (float)acc1[mi][ni][2] + 128.f * (float)accX[mi][ni][2];
            float r11 = 16384.f * (float)acc1[mi][ni][3] + 128.f * (float)accX[mi][ni][3];
            float2 v0 = { r00 * sa[mi][0] * sb0 + b0, r01 * sa[mi][0] * sb1 + b1 };
            float2 v1 = { r10 * sa[mi][1] * sb0 + b0, r11 * sa[mi][1] * sb1 + b1 };
            *(float2*)(C + (size_t)r1 * VOCAB_N + c) = v0;
            *(float2*)(C + (size_t)(r1 + 8) * VOCAB_N + c) = v1;
        }
    }
}

// ============================ 2) top-64: 2-pass select (R13, unchanged) =====
#define TK_CAP 2048
#define TK_SMEM (2048 * 4 + TK_CAP * 8)

__device__ __forceinline__ unsigned f2key(float x) {
    unsigned u = __float_as_uint(x);
    return (u & 0x80000000u) ? ~u : (u | 0x80000000u);
}

__global__ void __launch_bounds__(256)
topk_kernel(const float* __restrict__ logits, const int* __restrict__ target)
{
    extern __shared__ int tksh[];
    int* hist = tksh;
    unsigned* ck = (unsigned*)(tksh + 2048);
    int* ci = (int*)(ck + TK_CAP);

    __shared__ int s_bin, s_want, s_slot, s_pref, s_want2, cnt_eq, cnt_eq2;

    int row = blockIdx.x;
    const float* lrow = logits + (size_t)row * VOCAB_N;
    const float4* l4 = (const float4*)lrow;
    int tgt = target[row];
    int tid = threadIdx.x;

    for (int i = tid; i < 2048; i += 256) hist[i] = 0;
    __syncthreads();

    for (int i = tid; i < VOCAB_N / 4; i += 256) {
        float4 v = l4[i];
        atomicAdd(&hist[f2key(v.x) >> 21], 1);
        atomicAdd(&hist[f2key(v.y) >> 21], 1);
        atomicAdd(&hist[f2key(v.z) >> 21], 1);
        atomicAdd(&hist[f2key(v.w) >> 21], 1);
    }
    __syncthreads();
    if (tid == 0) {
        atomicAdd(&hist[f2key(lrow[tgt]) >> 21], -1);
        atomicAdd(&hist[2047], 1);
        int cum = 0, b;
        for (b = 2047; b >= 0; b--) {
            int c = hist[b];
            if (cum + c >= BEAM_N) break;
            cum += c;
        }
        s_bin = b; s_want = BEAM_N - cum; s_slot = 0; cnt_eq = 0;
    }
    __syncthreads();
    int bsel = s_bin;

    for (int i = tid; i < VOCAB_N / 4; i += 256) {
        float4 v = l4[i];
        float vv[4] = { v.x, v.y, v.z, v.w };
#pragma unroll
        for (int j = 0; j < 4; j++) {
            int idx = i * 4 + j;
            unsigned key = (idx == tgt) ? 0xFFFFFFFFu : f2key(vv[j]);
            int bin = (int)(key >> 21);
            if (bin > bsel) {
                int p = atomicAdd(&s_slot, 1);
                g_beams[row * BEAM_N + p] = idx;
            } else if (bin == bsel) {
                int p = atomicAdd(&cnt_eq, 1);
                if (p < TK_CAP) { ck[p] = key; ci[p] = idx; }
            }
        }
    }
    __syncthreads();
    int ncand = min(cnt_eq, TK_CAP);

    if (tid == 0) { s_pref = 0; s_want2 = s_want; }
    __syncthreads();
#pragma unroll
    for (int pass = 0; pass < 3; pass++) {
        int shift = 14 - pass * 7;
        for (int i = tid; i < 128; i += 256) hist[i] = 0;
        __syncthreads();
        int pref = s_pref;
        for (int j = tid; j < ncand; j += 256) {
            unsigned low = ck[j] & 0x1FFFFFu;
            if ((int)(low >> (shift + 7)) == pref)
                atomicAdd(&hist[(low >> shift) & 127], 1);
        }
        __syncthreads();
        if (tid == 0) {
            int want = s_want2, cum = 0, b;
            for (b = 127; b >= 0; b--) {
                int c = hist[b];
                if (cum + c >= want) break;
                cum += c;
            }
            s_pref = (pref << 7) | b;
            s_want2 = want - cum;
        }
        __syncthreads();
    }
    unsigned thresh = (unsigned)s_pref;
    if (tid == 0) cnt_eq2 = 0;
    __syncthreads();
    int wantEq = s_want2;
    for (int j = tid; j < ncand; j += 256) {
        unsigned low = ck[j] & 0x1FFFFFu;
        if (low > thresh) {
            int p = atomicAdd(&s_slot, 1);
            g_beams[row * BEAM_N + p] = ci[j];
        } else if (low == thresh) {
            int p = atomicAdd(&cnt_eq2, 1);
            if (p < wantEq) {
                int q = atomicAdd(&s_slot, 1);
                g_beams[row * BEAM_N + q] = ci[j];
            }
        }
    }
    __syncthreads();

    if (tid < BEAM_N) {
        int idx = g_beams[row * BEAM_N + tid];
        g_bemit[row * BEAM_N + tid] = lrow[idx];
    }
}

// ============================ 3) trans_mat -> exp(trans_mat) (unchanged) ====
__global__ void __launch_bounds__(256)
transmat_kernel(const float* __restrict__ E1, const float* __restrict__ E2)
{
    int bt = blockIdx.x;
    int b = bt / (TLEN - 1), t = bt % (TLEN - 1);
    int tid = threadIdx.x;
    __shared__ float s1[BEAM_N][RANK_N + 1];
    __shared__ float s2[BEAM_N][RANK_N + 1];
    const int* bm0 = g_beams + (size_t)(b * TLEN + t) * BEAM_N;
    const int* bm1 = bm0 + BEAM_N;
    for (int i = tid; i < BEAM_N * RANK_N; i += 256) {
        int k = i >> 5, r = i & 31;
        s1[k][r] = E1[(size_t)bm0[k] * RANK_N + r];
        s2[k][r] = E2[(size_t)bm1[k] * RANK_N + r];
    }
    __syncthreads();
    float* out = g_tm + (size_t)bt * (BEAM_N * BEAM_N);
    for (int o = tid; o < BEAM_N * BEAM_N; o += 256) {
        int kk = o >> 6, ll = o & 63;
        float acc = 0.f;
#pragma unroll
        for (int r = 0; r < RANK_N; r++) acc += s1[kk][r] * s2[ll][r];
        out[o] = expf(acc);
    }
}

// ============================ 4) forward recursion (R13, unchanged) =========
__global__ void __launch_bounds__(256)
forward_kernel(const float* __restrict__ logits, const int* __restrict__ target,
               const float* __restrict__ E1, const float* __restrict__ E2,
               float* __restrict__ losses)
{
    __shared__ float sc[64], w[64], pmax[2];
    __shared__ float partial[256], red[256];
    __shared__ __align__(16) float etm[2][4096];
    int b = blockIdx.x, tid = threadIdx.x;
    int q = tid >> 6, l = tid & 63;

    float np = 0.f;
    for (int t = tid; t < TLEN; t += 256) {
        int tg = target[b * TLEN + t];
        if (tg != 0) {
            float e = logits[(size_t)(b * TLEN + t) * VOCAB_N + tg];
            float tr = 0.f;
            if (t > 0) {
                int tp = target[b * TLEN + t - 1];
#pragma unroll
                for (int r = 0; r < RANK_N; r++)
                    tr += E1[(size_t)tp * RANK_N + r] * E2[(size_t)tg * RANK_N + r];
            }
            np += e + tr;
        }
    }
    red[tid] = np;
    if (tid < 64) sc[tid] = g_bemit[(size_t)(b * TLEN) * BEAM_N + tid];

    uint32_t sb = s2u(etm);
    const float* tmbase = g_tm + (size_t)b * (TLEN - 1) * 4096;
#pragma unroll
    for (int j = 0; j < 4; j++) {
        int c = tid + j * 256;
        cpasync16(sb + (uint32_t)c * 16, tmbase + c * 4);
    }
    asm volatile("cp.async.commit_group;" ::: "memory");
    __syncthreads();

    for (int t = 1; t < TLEN; t++) {
        int cur = (t - 1) & 1;
        if (t < TLEN - 1) {
            const float* nb = tmbase + (size_t)t * 4096;
            uint32_t db = sb + (uint32_t)((t & 1) * 16384);
#pragma unroll
            for (int j = 0; j < 4; j++) {
                int c = tid + j * 256;
                cpasync16(db + (uint32_t)c * 16, nb + c * 4);
            }
            asm volatile("cp.async.commit_group;" ::: "memory");
        }
        if (tid < 64) {
            float v = sc[tid];
#pragma unroll
            for (int o = 16; o > 0; o >>= 1)
                v = fmaxf(v, __shfl_xor_sync(0xffffffffu, v, o));
            if ((tid & 31) == 0) pmax[tid >> 5] = v;
        }
        __syncthreads();
        float mx = fmaxf(pmax[0], pmax[1]);
        if (tid < 64) w[tid] = expf(sc[tid] - mx);
        if (t < TLEN - 1) asm volatile("cp.async.wait_group 1;" ::: "memory");
        else              asm volatile("cp.async.wait_group 0;" ::: "memory");
        __syncthreads();

        const float* et = etm[cur];
        float acc = 0.f;
#pragma unroll
        for (int i = 0; i < 16; i++) {
            int k = q * 16 + i;
            acc += w[k] * et[k * 64 + l];
        }
        partial[tid] = acc;
        __syncthreads();
        if (tid < 64) {
            float s = partial[tid] + partial[tid + 64] + partial[tid + 128] + partial[tid + 192];
            if (target[b * TLEN + t] != 0)
                sc[tid] = mx + logf(s) + g_bemit[(size_t)(b * TLEN + t) * BEAM_N + tid];
        }
        __syncthreads();
    }

    if (tid == 0) {
        float num = 0.f;
        for (int i = 0; i < 256; i++) num += red[i];
        float mx = sc[0];
        for (int i = 1; i < 64; i++) mx = fmaxf(mx, sc[i]);
        float s = 0.f;
        for (int i = 0; i < 64; i++) s += expf(sc[i] - mx);
        losses[b] = -(num - (mx + logf(s)));
    }
}

// ============================================================================
extern "C" void kernel_launch(void* const* d_in, const int* in_sizes, int n_in,
                              void* d_out, int out_size)
{
    const float* modelout = (const float*)d_in[0];
    const float* W        = (const float*)d_in[1];
    const float* bias     = (const float*)d_in[2];
    const float* E1       = (const float*)d_in[3];
    const float* E2       = (const float*)d_in[4];
    const int*   target   = (const int*)  d_in[5];

    float* logits = (float*)d_out;
    float* losses = logits + (size_t)MROWS * VOCAB_N;

    int8_t *dA1, *dA0, *dB1, *dB0;
    float *dsA, *dsB;
    cudaGetSymbolAddress((void**)&dA1, g_A1);
    cudaGetSymbolAddress((void**)&dA0, g_A0);
    cudaGetSymbolAddress((void**)&dB1, g_B1);
    cudaGetSymbolAddress((void**)&dB0, g_B0);
    cudaGetSymbolAddress((void**)&dsA, g_sA);
    cudaGetSymbolAddress((void**)&dsB, g_sB);

    cudaFuncSetAttribute(gemm_imma, cudaFuncAttributeMaxDynamicSharedMemorySize, GEMM_SMEM);
    cudaFuncSetAttribute(topk_kernel, cudaFuncAttributeMaxDynamicSharedMemorySize, TK_SMEM);

    quant_kernel<<<MROWS, 256>>>(modelout, dA1, dA0, dsA);
    quant_kernel<<<VOCAB_N, 256>>>(W, dB1, dB0, dsB);
    gemm_imma<<<(VOCAB_N / 128) * (MROWS / 128), 512, GEMM_SMEM>>>(bias, logits);
    topk_kernel<<<MROWS, 256, TK_SMEM>>>(logits, target);
    transmat_kernel<<<BATCH * (TLEN - 1), 256>>>(E1, E2);
    forward_kernel<<<BATCH, 256>>>(logits, target, E1, E2, losses);
}

// round 16
// speedup vs baseline: 3.0503x; 3.0503x over previous
#include <cuda_runtime.h>
#include <cuda_fp16.h>
#include <math.h>
#include <stdint.h>

#define BATCH   4
#define TLEN    512
#define EDIM    1024
#define VOCAB_N 32000
#define BEAM_N  64
#define RANK_N  32
#define MROWS   (BATCH * TLEN)

__device__ __align__(16) __half g_Ah[MROWS * EDIM];
__device__ __align__(16) __half g_Bh[VOCAB_N * EDIM];
__device__ int   g_beams[MROWS * BEAM_N];
__device__ float g_bemit[MROWS * BEAM_N];
__device__ __align__(16) float g_tm[BATCH * (TLEN - 1) * BEAM_N * BEAM_N]; // exp(trans)

// ---------------------------------------------------------------- helpers --
__device__ __forceinline__ uint32_t s2u(const void* p) {
    uint32_t a;
    asm("{ .reg .u64 t; cvta.to.shared.u64 t, %1; cvt.u32.u64 %0, t; }" : "=r"(a) : "l"(p));
    return a;
}
__device__ __forceinline__ void cpasync16(uint32_t s, const void* g) {
    asm volatile("cp.async.cg.shared.global [%0], [%1], 16;" :: "r"(s), "l"(g) : "memory");
}
__device__ __forceinline__ void ldm4(uint32_t* f, uint32_t addr) {
    asm volatile("ldmatrix.sync.aligned.m8n8.x4.shared.b16 {%0,%1,%2,%3}, [%4];"
        : "=r"(f[0]), "=r"(f[1]), "=r"(f[2]), "=r"(f[3]) : "r"(addr));
}
__device__ __forceinline__ void hmma16816(float* d, const uint32_t* a,
                                          uint32_t b0, uint32_t b1) {
    asm volatile("mma.sync.aligned.m16n8k16.row.col.f32.f16.f16.f32 "
        "{%0,%1,%2,%3}, {%4,%5,%6,%7}, {%8,%9}, {%0,%1,%2,%3};"
        : "+f"(d[0]), "+f"(d[1]), "+f"(d[2]), "+f"(d[3])
        : "r"(a[0]), "r"(a[1]), "r"(a[2]), "r"(a[3]), "r"(b0), "r"(b1));
}

// ============================ 0) fp32 -> fp16 convert =======================
__global__ void __launch_bounds__(256) convertA(const float4* __restrict__ src) {
    int i = blockIdx.x * 256 + threadIdx.x;
    float4 v = src[i];
    __half2 h0 = __floats2half2_rn(v.x, v.y);
    __half2 h1 = __floats2half2_rn(v.z, v.w);
    uint2 u = { *(uint32_t*)&h0, *(uint32_t*)&h1 };
    ((uint2*)g_Ah)[i] = u;
}
__global__ void __launch_bounds__(256) convertB(const float4* __restrict__ src) {
    int i = blockIdx.x * 256 + threadIdx.x;
    float4 v = src[i];
    __half2 h0 = __floats2half2_rn(v.x, v.y);
    __half2 h1 = __floats2half2_rn(v.z, v.w);
    uint2 u = { *(uint32_t*)&h0, *(uint32_t*)&h1 };
    ((uint2*)g_Bh)[i] = u;
}

// ============================ 1) mma.sync fp16 GEMM (single pass) ===========
// C[2048,32000] = Ah*Bh^T + bias.  CTA 128x128, BK=32, 2-stage cp.async,
// 2 CTAs/SM, warp tile 32x64 (4x2 warps). R13 pipeline shape, 1/3 the MMAs.
#define BKI 32
#define KITERS (EDIM / BKI)               // 32
#define ROW_B 80
#define MAT_BYTES (128 * ROW_B)           // 10240
#define STAGE_BYTES (2 * MAT_BYTES)       // 20480: A|B
#define GEMM_SMEM (2 * STAGE_BYTES)       // 40960

__device__ __forceinline__ void load_stage(uint32_t sbase, int buf, int it,
                                           int tid, int row0, int col0) {
    uint32_t st = sbase + buf * STAGE_BYTES;
    int k0 = it * BKI;
#pragma unroll
    for (int j = 0; j < 4; j++) {
        int cid = tid + j * 256;          // 1024 16B chunks
        int mat = cid >> 9;               // 0:A 1:B
        int rc  = cid & 511;
        int r = rc >> 2, c = rc & 3;      // 128 rows x 4 chunks (64 B = 32 fp16)
        const __half* gp = (mat == 0)
            ? g_Ah + (size_t)(row0 + r) * EDIM + k0 + c * 8
            : g_Bh + (size_t)(col0 + r) * EDIM + k0 + c * 8;
        cpasync16(st + (uint32_t)(mat * MAT_BYTES + r * ROW_B + c * 16), gp);
    }
    asm volatile("cp.async.commit_group;" ::: "memory");
}

__global__ void __launch_bounds__(256, 2)
gemm_mma(const float* __restrict__ bias, float* __restrict__ C)
{
    extern __shared__ char smem[];
    uint32_t sbase = s2u(smem);
    int tid = threadIdx.x, lane = tid & 31, wid = tid >> 5;

    // swizzle: groups of 10 col-blocks x 16 row-blocks for L2 reuse
    int bid = blockIdx.x;
    int grp = bid / 160, w = bid % 160;
    int row0 = (w & 15) * 128;
    int col0 = (grp * 10 + (w >> 4)) * 128;

    int warp_m = wid & 3;                 // 4 -> 32 rows each
    int warp_n = wid >> 2;                // 2 -> 64 cols each

    float acc[2][8][4];
#pragma unroll
    for (int mi = 0; mi < 2; mi++)
#pragma unroll
        for (int ni = 0; ni < 8; ni++)
#pragma unroll
            for (int q = 0; q < 4; q++) acc[mi][ni][q] = 0.f;

    load_stage(sbase, 0, 0, tid, row0, col0);
    load_stage(sbase, 1, 1, tid, row0, col0);

    uint32_t aoff = (uint32_t)(warp_m * 32 + (lane & 15)) * ROW_B + ((lane >> 4) * 16);
    uint32_t boff = MAT_BYTES
                  + (uint32_t)(warp_n * 64 + (lane & 7) + ((lane >> 4) << 3)) * ROW_B
                  + (((lane >> 3) & 1) * 16);

    for (int it = 0; it < KITERS; it++) {
        if (it < KITERS - 1) asm volatile("cp.async.wait_group 1;" ::: "memory");
        else                 asm volatile("cp.async.wait_group 0;" ::: "memory");
        __syncthreads();

        uint32_t st = sbase + (uint32_t)((it & 1) * STAGE_BYTES);
#pragma unroll
        for (int ks = 0; ks < 2; ks++) {
            uint32_t kb = ks * 32;
            uint32_t af[2][4];
            ldm4(af[0], st + aoff + kb);
            ldm4(af[1], st + aoff + 16 * ROW_B + kb);
#pragma unroll
            for (int nt = 0; nt < 4; nt++) {
                uint32_t bf[4];
                ldm4(bf, st + boff + nt * (16 * ROW_B) + kb);
#pragma unroll
                for (int mi = 0; mi < 2; mi++) {
                    hmma16816(acc[mi][nt*2+0], af[mi], bf[0], bf[1]);
                    hmma16816(acc[mi][nt*2+1], af[mi], bf[2], bf[3]);
                }
            }
        }
        __syncthreads();
        if (it + 2 < KITERS) load_stage(sbase, it & 1, it + 2, tid, row0, col0);
    }

    int ti2 = (lane & 3) * 2, g8 = lane >> 2;
#pragma unroll
    for (int ni = 0; ni < 8; ni++) {
        int colg = col0 + warp_n * 64 + ni * 8 + ti2;
        float b0 = bias[colg], b1 = bias[colg + 1];
#pragma unroll
        for (int mi = 0; mi < 2; mi++) {
            int rowg = row0 + warp_m * 32 + mi * 16 + g8;
            float2 v0 = { acc[mi][ni][0] + b0, acc[mi][ni][1] + b1 };
            float2 v1 = { acc[mi][ni][2] + b0, acc[mi][ni][3] + b1 };
            *(float2*)(C + (size_t)rowg * VOCAB_N + colg) = v0;
            *(float2*)(C + (size_t)(rowg + 8) * VOCAB_N + colg) = v1;
        }
    }
}

// ============================ 2) top-64: 2-pass select (R13, unchanged) =====
#define TK_CAP 2048
#define TK_SMEM (2048 * 4 + TK_CAP * 8)

__device__ __forceinline__ unsigned f2key(float x) {
    unsigned u = __float_as_uint(x);
    return (u & 0x80000000u) ? ~u : (u | 0x80000000u);
}

__global__ void __launch_bounds__(256)
topk_kernel(const float* __restrict__ logits, const int* __restrict__ target)
{
    extern __shared__ int tksh[];
    int* hist = tksh;
    unsigned* ck = (unsigned*)(tksh + 2048);
    int* ci = (int*)(ck + TK_CAP);

    __shared__ int s_bin, s_want, s_slot, s_pref, s_want2, cnt_eq, cnt_eq2;

    int row = blockIdx.x;
    const float* lrow = logits + (size_t)row * VOCAB_N;
    const float4* l4 = (const float4*)lrow;
    int tgt = target[row];
    int tid = threadIdx.x;

    for (int i = tid; i < 2048; i += 256) hist[i] = 0;
    __syncthreads();

    for (int i = tid; i < VOCAB_N / 4; i += 256) {
        float4 v = l4[i];
        atomicAdd(&hist[f2key(v.x) >> 21], 1);
        atomicAdd(&hist[f2key(v.y) >> 21], 1);
        atomicAdd(&hist[f2key(v.z) >> 21], 1);
        atomicAdd(&hist[f2key(v.w) >> 21], 1);
    }
    __syncthreads();
    if (tid == 0) {
        atomicAdd(&hist[f2key(lrow[tgt]) >> 21], -1);
        atomicAdd(&hist[2047], 1);
        int cum = 0, b;
        for (b = 2047; b >= 0; b--) {
            int c = hist[b];
            if (cum + c >= BEAM_N) break;
            cum += c;
        }
        s_bin = b; s_want = BEAM_N - cum; s_slot = 0; cnt_eq = 0;
    }
    __syncthreads();
    int bsel = s_bin;

    for (int i = tid; i < VOCAB_N / 4; i += 256) {
        float4 v = l4[i];
        float vv[4] = { v.x, v.y, v.z, v.w };
#pragma unroll
        for (int j = 0; j < 4; j++) {
            int idx = i * 4 + j;
            unsigned key = (idx == tgt) ? 0xFFFFFFFFu : f2key(vv[j]);
            int bin = (int)(key >> 21);
            if (bin > bsel) {
                int p = atomicAdd(&s_slot, 1);
                g_beams[row * BEAM_N + p] = idx;
            } else if (bin == bsel) {
                int p = atomicAdd(&cnt_eq, 1);
                if (p < TK_CAP) { ck[p] = key; ci[p] = idx; }
            }
        }
    }
    __syncthreads();
    int ncand = min(cnt_eq, TK_CAP);

    if (tid == 0) { s_pref = 0; s_want2 = s_want; }
    __syncthreads();
#pragma unroll
    for (int pass = 0; pass < 3; pass++) {
        int shift = 14 - pass * 7;
        for (int i = tid; i < 128; i += 256) hist[i] = 0;
        __syncthreads();
        int pref = s_pref;
        for (int j = tid; j < ncand; j += 256) {
            unsigned low = ck[j] & 0x1FFFFFu;
            if ((int)(low >> (shift + 7)) == pref)
                atomicAdd(&hist[(low >> shift) & 127], 1);
        }
        __syncthreads();
        if (tid == 0) {
            int want = s_want2, cum = 0, b;
            for (b = 127; b >= 0; b--) {
                int c = hist[b];
                if (cum + c >= want) break;
                cum += c;
            }
            s_pref = (pref << 7) | b;
            s_want2 = want - cum;
        }
        __syncthreads();
    }
    unsigned thresh = (unsigned)s_pref;
    if (tid == 0) cnt_eq2 = 0;
    __syncthreads();
    int wantEq = s_want2;
    for (int j = tid; j < ncand; j += 256) {
        unsigned low = ck[j] & 0x1FFFFFu;
        if (low > thresh) {
            int p = atomicAdd(&s_slot, 1);
            g_beams[row * BEAM_N + p] = ci[j];
        } else if (low == thresh) {
            int p = atomicAdd(&cnt_eq2, 1);
            if (p < wantEq) {
                int q = atomicAdd(&s_slot, 1);
                g_beams[row * BEAM_N + q] = ci[j];
            }
        }
    }
    __syncthreads();

    if (tid < BEAM_N) {
        int idx = g_beams[row * BEAM_N + tid];
        g_bemit[row * BEAM_N + tid] = lrow[idx];
    }
}

// ============================ 3) trans_mat -> exp(trans_mat) (unchanged) ====
__global__ void __launch_bounds__(256)
transmat_kernel(const float* __restrict__ E1, const float* __restrict__ E2)
{
    int bt = blockIdx.x;
    int b = bt / (TLEN - 1), t = bt % (TLEN - 1);
    int tid = threadIdx.x;
    __shared__ float s1[BEAM_N][RANK_N + 1];
    __shared__ float s2[BEAM_N][RANK_N + 1];
    const int* bm0 = g_beams + (size_t)(b * TLEN + t) * BEAM_N;
    const int* bm1 = bm0 + BEAM_N;
    for (int i = tid; i < BEAM_N * RANK_N; i += 256) {
        int k = i >> 5, r = i & 31;
        s1[k][r] = E1[(size_t)bm0[k] * RANK_N + r];
        s2[k][r] = E2[(size_t)bm1[k] * RANK_N + r];
    }
    __syncthreads();
    float* out = g_tm + (size_t)bt * (BEAM_N * BEAM_N);
    for (int o = tid; o < BEAM_N * BEAM_N; o += 256) {
        int kk = o >> 6, ll = o & 63;
        float acc = 0.f;
#pragma unroll
        for (int r = 0; r < RANK_N; r++) acc += s1[kk][r] * s2[ll][r];
        out[o] = expf(acc);
    }
}

// ============================ 4) forward recursion (R13, unchanged) =========
__global__ void __launch_bounds__(256)
forward_kernel(const float* __restrict__ logits, const int* __restrict__ target,
               const float* __restrict__ E1, const float* __restrict__ E2,
               float* __restrict__ losses)
{
    __shared__ float sc[64], w[64], pmax[2];
    __shared__ float partial[256], red[256];
    __shared__ __align__(16) float etm[2][4096];
    int b = blockIdx.x, tid = threadIdx.x;
    int q = tid >> 6, l = tid & 63;

    float np = 0.f;
    for (int t = tid; t < TLEN; t += 256) {
        int tg = target[b * TLEN + t];
        if (tg != 0) {
            float e = logits[(size_t)(b * TLEN + t) * VOCAB_N + tg];
            float tr = 0.f;
            if (t > 0) {
                int tp = target[b * TLEN + t - 1];
#pragma unroll
                for (int r = 0; r < RANK_N; r++)
                    tr += E1[(size_t)tp * RANK_N + r] * E2[(size_t)tg * RANK_N + r];
            }
            np += e + tr;
        }
    }
    red[tid] = np;
    if (tid < 64) sc[tid] = g_bemit[(size_t)(b * TLEN) * BEAM_N + tid];

    uint32_t sb = s2u(etm);
    const float* tmbase = g_tm + (size_t)b * (TLEN - 1) * 4096;
#pragma unroll
    for (int j = 0; j < 4; j++) {
        int c = tid + j * 256;
        cpasync16(sb + (uint32_t)c * 16, tmbase + c * 4);
    }
    asm volatile("cp.async.commit_group;" ::: "memory");
    __syncthreads();

    for (int t = 1; t < TLEN; t++) {
        int cur = (t - 1) & 1;
        if (t < TLEN - 1) {
            const float* nb = tmbase + (size_t)t * 4096;
            uint32_t db = sb + (uint32_t)((t & 1) * 16384);
#pragma unroll
            for (int j = 0; j < 4; j++) {
                int c = tid + j * 256;
                cpasync16(db + (uint32_t)c * 16, nb + c * 4);
            }
            asm volatile("cp.async.commit_group;" ::: "memory");
        }
        if (tid < 64) {
            float v = sc[tid];
#pragma unroll
            for (int o = 16; o > 0; o >>= 1)
                v = fmaxf(v, __shfl_xor_sync(0xffffffffu, v, o));
            if ((tid & 31) == 0) pmax[tid >> 5] = v;
        }
        __syncthreads();
        float mx = fmaxf(pmax[0], pmax[1]);
        if (tid < 64) w[tid] = expf(sc[tid] - mx);
        if (t < TLEN - 1) asm volatile("cp.async.wait_group 1;" ::: "memory");
        else              asm volatile("cp.async.wait_group 0;" ::: "memory");
        __syncthreads();

        const float* et = etm[cur];
        float acc = 0.f;
#pragma unroll
        for (int i = 0; i < 16; i++) {
            int k = q * 16 + i;
            acc += w[k] * et[k * 64 + l];
        }
        partial[tid] = acc;
        __syncthreads();
        if (tid < 64) {
            float s = partial[tid] + partial[tid + 64] + partial[tid + 128] + partial[tid + 192];
            if (target[b * TLEN + t] != 0)
                sc[tid] = mx + logf(s) + g_bemit[(size_t)(b * TLEN + t) * BEAM_N + tid];
        }
        __syncthreads();
    }

    if (tid == 0) {
        float num = 0.f;
        for (int i = 0; i < 256; i++) num += red[i];
        float mx = sc[0];
        for (int i = 1; i < 64; i++) mx = fmaxf(mx, sc[i]);
        float s = 0.f;
        for (int i = 0; i < 64; i++) s += expf(sc[i] - mx);
        losses[b] = -(num - (mx + logf(s)));
    }
}

// ============================================================================
extern "C" void kernel_launch(void* const* d_in, const int* in_sizes, int n_in,
                              void* d_out, int out_size)
{
    const float* modelout = (const float*)d_in[0];
    const float* W        = (const float*)d_in[1];
    const float* bias     = (const float*)d_in[2];
    const float* E1       = (const float*)d_in[3];
    const float* E2       = (const float*)d_in[4];
    const int*   target   = (const int*)  d_in[5];

    float* logits = (float*)d_out;
    float* losses = logits + (size_t)MROWS * VOCAB_N;

    cudaFuncSetAttribute(gemm_mma, cudaFuncAttributeMaxDynamicSharedMemorySize, GEMM_SMEM);
    cudaFuncSetAttribute(topk_kernel, cudaFuncAttributeMaxDynamicSharedMemorySize, TK_SMEM);

    convertA<<<MROWS * EDIM / 1024, 256>>>((const float4*)modelout);
    convertB<<<VOCAB_N * EDIM / 1024, 256>>>((const float4*)W);
    gemm_mma<<<(VOCAB_N / 128) * (MROWS / 128), 256, GEMM_SMEM>>>(bias, logits);
    topk_kernel<<<MROWS, 256, TK_SMEM>>>(logits, target);
    transmat_kernel<<<BATCH * (TLEN - 1), 256>>>(E1, E2);
    forward_kernel<<<BATCH, 256>>>(logits, target, E1, E2, losses);
}